// round 13
// baseline (speedup 1.0000x reference)
#include <cuda_runtime.h>
#include <cuda_fp16.h>
#include <cstdint>

#define N_NODES 100000
#define N_EDGES 1600000
#define IN_CH   256
#define HID     128
#define PAD     96          // max in-degree bucket (Poisson(16): P(>=96) ~ e^-92)
#define NBIN    97          // degree bins 0..96

// ---------------- device scratch (no runtime allocation allowed) -------------
__device__ __half g_hh[(size_t)N_NODES * HID];  // x@W (unscaled), fp16
__device__ float  g_dinv[N_NODES];
__device__ int    g_cur[N_NODES];               // in-degree counters / cursors
__device__ int    g_psrc[(size_t)N_NODES * PAD];// padded neighbor lists
__device__ int    g_order[N_NODES];             // nodes sorted by degree
__device__ int    g_hist[128];                  // degree histogram
__device__ int    g_bcur[128];                  // bin cursors (prefix sums)
__device__ int    g_is64;
__device__ __half g_wt[HID * IN_CH];            // W^T fp16: [n][k]

// ---------------- 1. setup: zero counters/hist + detect dtype + convert W ------
__global__ void setup_kernel(const int* __restrict__ ei32,
                             const float* __restrict__ W) {
    int i = blockIdx.x * blockDim.x + threadIdx.x;
    if (i < N_NODES) g_cur[i] = 0;
    if (i < 128) g_hist[i] = 0;
    if (i < HID * IN_CH) {
        int n = i >> 8;           // 0..127
        int k = i & 255;          // 0..255
        g_wt[i] = __float2half_rn(W[k * HID + n]);
    }
    if (i == 0) {
        int all_zero = 1;
#pragma unroll
        for (int j = 0; j < 8; j++)
            if (ei32[2 * j + 1] != 0) all_zero = 0;
        g_is64 = all_zero;
    }
}

// ---------------- 2. bucket-fill padded neighbor lists -------------------------
__global__ void fill_kernel(const int* __restrict__ ei32,
                            const long long* __restrict__ ei64) {
    int e = blockIdx.x * blockDim.x + threadIdx.x;
    if (e < N_EDGES) {
        int r, c;
        if (g_is64) {
            r = (int)ei64[e];
            c = (int)ei64[N_EDGES + e];
        } else {
            r = ei32[e];
            c = ei32[N_EDGES + e];
        }
        int p = atomicAdd(&g_cur[c], 1);
        if (p < PAD) g_psrc[(size_t)c * PAD + p] = r;
    }
}

// ---------------- 3. counters -> dinv + degree histogram -----------------------
__global__ void dinv_kernel() {
    int i = blockIdx.x * blockDim.x + threadIdx.x;
    if (i < N_NODES) {
        int d = g_cur[i];
        g_dinv[i] = rsqrtf((float)(d + 1));  // +1 self loop
        atomicAdd(&g_hist[d < PAD ? d : PAD], 1);
    }
}

// ---------------- 4. exclusive scan of 97 bins (one block) ---------------------
__global__ void scan_kernel() {
    __shared__ int wsc[4];
    int t = threadIdx.x;          // 128 threads
    int v = (t < NBIN) ? g_hist[t] : 0;
    int lane = t & 31, w = t >> 5;
    int incl = v;
#pragma unroll
    for (int o = 1; o < 32; o <<= 1) {
        int u = __shfl_up_sync(0xffffffffu, incl, o);
        if (lane >= o) incl += u;
    }
    if (lane == 31) wsc[w] = incl;
    __syncthreads();
    if (w == 0 && lane < 4) {
        int s = wsc[lane];
        int si = s;
#pragma unroll
        for (int o = 1; o < 4; o <<= 1) {
            int u = __shfl_up_sync(0xfu, si, o);
            if (lane >= o) si += u;
        }
        wsc[lane] = si - s;
    }
    __syncthreads();
    if (t < NBIN) g_bcur[t] = wsc[w] + incl - v;   // exclusive prefix
}

// ---------------- 5. scatter nodes into degree-sorted order --------------------
__global__ void order_kernel() {
    int i = blockIdx.x * blockDim.x + threadIdx.x;
    if (i < N_NODES) {
        int d = g_cur[i];
        if (d > PAD) d = PAD;
        int pos = atomicAdd(&g_bcur[d], 1);
        g_order[pos] = i;
    }
}

// ---------------- 6. HMMA GEMM: hh = x @ W (fp16 single-term) -----------------
#define KCH    32
#define NCHUNK (IN_CH / KCH)     // 8
#define LDA    40                // padded row: 80B (conflict-free for ldmatrix)
#define B_B    10240             // B tile byte offset within buffer
#define BUF_B  20480
#define GEMM_SMEM (2 * BUF_B)    // 40960 bytes

__device__ __forceinline__ uint32_t s2u(const void* p) {
    uint32_t a;
    asm("{ .reg .u64 t; cvta.to.shared.u64 t, %1; cvt.u32.u64 %0, t; }"
        : "=r"(a) : "l"(p));
    return a;
}
__device__ __forceinline__ void ldsm4(uint32_t& r0, uint32_t& r1,
                                      uint32_t& r2, uint32_t& r3, uint32_t a) {
    asm volatile("ldmatrix.sync.aligned.m8n8.x4.shared.b16 {%0,%1,%2,%3}, [%4];"
                 : "=r"(r0), "=r"(r1), "=r"(r2), "=r"(r3) : "r"(a));
}
__device__ __forceinline__ void mma_f16(float* c, const uint32_t* a,
                                        const uint32_t* b) {
    asm volatile(
        "mma.sync.aligned.m16n8k16.row.col.f32.f16.f16.f32 "
        "{%0,%1,%2,%3}, {%4,%5,%6,%7}, {%8,%9}, {%0,%1,%2,%3};"
        : "+f"(c[0]), "+f"(c[1]), "+f"(c[2]), "+f"(c[3])
        : "r"(a[0]), "r"(a[1]), "r"(a[2]), "r"(a[3]), "r"(b[0]), "r"(b[1]));
}
__device__ __forceinline__ void cpa16(uint32_t dst, const void* src) {
    asm volatile("cp.async.ca.shared.global [%0], [%1], 16;"
                 :: "r"(dst), "l"(src) : "memory");
}
__device__ __forceinline__ uint32_t pack_h(float x, float y) {
    __half2 h = __floats2half2_rn(x, y);
    return *(uint32_t*)&h;
}

__global__ __launch_bounds__(256, 2) void gemm_hmma(const float* __restrict__ x) {
    extern __shared__ char sm[];
    const uint32_t smb = s2u(sm);

    const int t    = threadIdx.x;
    const int w    = t >> 5;
    const int l    = t & 31;
    const int wm   = w >> 2;         // 0..1
    const int wn   = w & 3;          // 0..3
    const int row0 = blockIdx.x * 128;

    float acc[4][4][4];
#pragma unroll
    for (int i = 0; i < 4; i++)
#pragma unroll
        for (int j = 0; j < 4; j++)
#pragma unroll
            for (int r = 0; r < 4; r++) acc[i][j][r] = 0.f;

    // ---- x staging: warp-contiguous. thread -> (row base rb, quad q) ----
    const int q  = l & 7;                 // 0..7 : 16B quad within the 128B piece
    const int rb = w * 4 + (l >> 3);      // 0..31
    const float4* xsrc = (const float4*)(x + (size_t)(row0 + rb) * IN_CH) + q;
    bool av[4];
    uint32_t ast[4];
#pragma unroll
    for (int i = 0; i < 4; i++) {
        av[i]  = (row0 + rb + 32 * i) < N_NODES;
        ast[i] = (uint32_t)((rb + 32 * i) * 80 + q * 8);
    }

    // ---- W staging via cp.async ----
    const __half* w_src = g_wt + (t >> 1) * IN_CH + (t & 1) * 16;
    const uint32_t b_st = smb + B_B + (uint32_t)((t >> 1) * 80 + (t & 1) * 32);

    // ldmatrix per-lane base addresses (bytes within buffer 0)
    const int a_row = wm * 64 + (l & 15);
    const int a_k   = (l >> 4) * 8;
    const int b_row = wn * 32 + (l & 7) + ((l >> 4) << 3);
    const int b_k   = ((l >> 3) & 1) * 8;
    const uint32_t aH = smb + (a_row * LDA + a_k) * 2;
    const uint32_t bH = smb + B_B + (b_row * LDA + b_k) * 2;

    float4 xa[4];
#pragma unroll
    for (int i = 0; i < 4; i++) xa[i] = make_float4(0.f, 0.f, 0.f, 0.f);

    // ---- prologue: chunk 0 ----
    cpa16(b_st,      w_src);
    cpa16(b_st + 16, w_src + 8);
    asm volatile("cp.async.commit_group;" ::: "memory");
#pragma unroll
    for (int i = 0; i < 4; i++)
        if (av[i]) xa[i] = xsrc[i * 2048];
#pragma unroll
    for (int i = 0; i < 4; i++)
        *(uint2*)(sm + ast[i]) =
            make_uint2(pack_h(xa[i].x, xa[i].y), pack_h(xa[i].z, xa[i].w));
    asm volatile("cp.async.wait_group 0;" ::: "memory");
    __syncthreads();

    for (int c = 0; c < NCHUNK; c++) {
        const uint32_t cur = (uint32_t)(c & 1) * BUF_B;
        const uint32_t nxt = (uint32_t)((c + 1) & 1) * BUF_B;

        if (c < NCHUNK - 1) {
            const __half* wn_src = w_src + (c + 1) * KCH;
            cpa16(b_st + nxt,      wn_src);
            cpa16(b_st + nxt + 16, wn_src + 8);
            asm volatile("cp.async.commit_group;" ::: "memory");
#pragma unroll
            for (int i = 0; i < 4; i++)
                if (av[i]) xa[i] = xsrc[(c + 1) * 8 + i * 2048];
        }

        // ---- 2 k16 steps of MMAs on buffer `cur` ----
#pragma unroll
        for (int kk = 0; kk < 2; kk++) {
            const uint32_t kb = cur + kk * 32;
            uint32_t bh[4][2];
#pragma unroll
            for (int jp = 0; jp < 2; jp++) {
                const uint32_t off = kb + jp * 1280;   // 16 rows * 80B
                ldsm4(bh[2*jp][0], bh[2*jp][1], bh[2*jp+1][0], bh[2*jp+1][1],
                      bH + off);
            }
#pragma unroll
            for (int mi = 0; mi < 4; mi++) {
                const uint32_t off = kb + mi * 1280;
                uint32_t ah[4];
                ldsm4(ah[0], ah[1], ah[2], ah[3], aH + off);
#pragma unroll
                for (int nj = 0; nj < 4; nj++)
                    mma_f16(acc[mi][nj], ah, bh[nj]);
            }
        }

        if (c < NCHUNK - 1) {
#pragma unroll
            for (int i = 0; i < 4; i++)
                *(uint2*)(sm + nxt + ast[i]) =
                    make_uint2(pack_h(xa[i].x, xa[i].y), pack_h(xa[i].z, xa[i].w));
            asm volatile("cp.async.wait_group 0;" ::: "memory");
        }
        __syncthreads();
    }

    // ---- epilogue: fp16 store ----
    const int mrow = row0 + wm * 64 + (l >> 2);
    const int ncol = wn * 32 + (l & 3) * 2;
#pragma unroll
    for (int mi = 0; mi < 4; mi++) {
        const int r0 = mrow + mi * 16;
        const int r1 = r0 + 8;
#pragma unroll
        for (int nj = 0; nj < 4; nj++) {
            const int n0 = ncol + nj * 8;
            if (r0 < N_NODES)
                *(__half2*)(g_hh + (size_t)r0 * HID + n0) =
                    __floats2half2_rn(acc[mi][nj][0], acc[mi][nj][1]);
            if (r1 < N_NODES)
                *(__half2*)(g_hh + (size_t)r1 * HID + n0) =
                    __floats2half2_rn(acc[mi][nj][2], acc[mi][nj][3]);
        }
    }
}

// ---------------- 7. aggregate + bias + PReLU ----------------------------------
// Half-warp (16 lanes) per node, nodes in degree-sorted order (g_order):
// paired half-warps have equal trip counts -> no divergence; unroll-8 -> 16
// gathers in flight per warp.
__device__ __forceinline__ void h8(const uint4& u, float* f) {
    float2 p;
    p = __half22float2(*(const __half2*)&u.x); f[0] = p.x; f[1] = p.y;
    p = __half22float2(*(const __half2*)&u.y); f[2] = p.x; f[3] = p.y;
    p = __half22float2(*(const __half2*)&u.z); f[4] = p.x; f[5] = p.y;
    p = __half22float2(*(const __half2*)&u.w); f[6] = p.x; f[7] = p.y;
}

__global__ __launch_bounds__(256) void agg_kernel(const float* __restrict__ bias,
                                                  const float* __restrict__ alpha,
                                                  float* __restrict__ out) {
    int k    = (blockIdx.x * blockDim.x + threadIdx.x) >> 4;
    int lane = threadIdx.x & 15;
    if (k >= N_NODES) return;
    int node = g_order[k];

    const uint4* __restrict__ hhv = (const uint4*)g_hh;   // 16 uint4 per row
    int cnt = g_cur[node];
    if (cnt > PAD) cnt = PAD;
    const float di = g_dinv[node];
    const int*  nb = g_psrc + (size_t)node * PAD;

    // self-loop seed: h[i] * dinv[i]
    float acc[8], f[8];
    uint4 su = hhv[(size_t)node * 16 + lane];
    h8(su, acc);
#pragma unroll
    for (int i = 0; i < 8; i++) acc[i] *= di;

    int e = 0;
    for (; e + 8 <= cnt; e += 8) {
        int j[8]; uint4 u[8]; float dd[8];
#pragma unroll
        for (int i = 0; i < 8; i++) j[i] = nb[e + i];
#pragma unroll
        for (int i = 0; i < 8; i++) u[i] = hhv[(size_t)j[i] * 16 + lane];
#pragma unroll
        for (int i = 0; i < 8; i++) dd[i] = g_dinv[j[i]];
#pragma unroll
        for (int i = 0; i < 8; i++) {
            h8(u[i], f);
#pragma unroll
            for (int c = 0; c < 8; c++) acc[c] += f[c] * dd[i];
        }
    }
    for (; e + 2 <= cnt; e += 2) {
        int j0 = nb[e], j1 = nb[e + 1];
        uint4 u0 = hhv[(size_t)j0 * 16 + lane];
        uint4 u1 = hhv[(size_t)j1 * 16 + lane];
        float d0 = g_dinv[j0], d1 = g_dinv[j1];
        h8(u0, f);
#pragma unroll
        for (int c = 0; c < 8; c++) acc[c] += f[c] * d0;
        h8(u1, f);
#pragma unroll
        for (int c = 0; c < 8; c++) acc[c] += f[c] * d1;
    }
    if (e < cnt) {
        int j = nb[e];
        uint4 u = hhv[(size_t)j * 16 + lane];
        float dj = g_dinv[j];
        h8(u, f);
#pragma unroll
        for (int c = 0; c < 8; c++) acc[c] += f[c] * dj;
    }

    float4 b0 = ((const float4*)bias)[lane * 2];
    float4 b1 = ((const float4*)bias)[lane * 2 + 1];
    float4 a0 = ((const float4*)alpha)[lane * 2];
    float4 a1 = ((const float4*)alpha)[lane * 2 + 1];

    float4 r0, r1;
    r0.x = di * acc[0] + b0.x;  r0.x = (r0.x > 0.f) ? r0.x : a0.x * r0.x;
    r0.y = di * acc[1] + b0.y;  r0.y = (r0.y > 0.f) ? r0.y : a0.y * r0.y;
    r0.z = di * acc[2] + b0.z;  r0.z = (r0.z > 0.f) ? r0.z : a0.z * r0.z;
    r0.w = di * acc[3] + b0.w;  r0.w = (r0.w > 0.f) ? r0.w : a0.w * r0.w;
    r1.x = di * acc[4] + b1.x;  r1.x = (r1.x > 0.f) ? r1.x : a1.x * r1.x;
    r1.y = di * acc[5] + b1.y;  r1.y = (r1.y > 0.f) ? r1.y : a1.y * r1.y;
    r1.z = di * acc[6] + b1.z;  r1.z = (r1.z > 0.f) ? r1.z : a1.z * r1.z;
    r1.w = di * acc[7] + b1.w;  r1.w = (r1.w > 0.f) ? r1.w : a1.w * r1.w;

    ((float4*)out)[(size_t)node * 32 + lane * 2]     = r0;
    ((float4*)out)[(size_t)node * 32 + lane * 2 + 1] = r1;
}

// ---------------- launch --------------------------------------------------------
// Fork: gemm (tensor/L1-bound) runs concurrently with the graph branch
// (fill -> dinv+hist -> scan -> order; L2-atomic-bound). Streams/events are
// created per call and NOT destroyed (destroying a capturing stream invalidates
// the capture; kernel_launch runs only ~twice, leak is bounded + host-side).
extern "C" void kernel_launch(void* const* d_in, const int* in_sizes, int n_in,
                              void* d_out, int out_size) {
    const float*     x     = (const float*)d_in[0];
    const int*       ei32  = (const int*)d_in[1];
    const long long* ei64  = (const long long*)d_in[1];
    const float*     W     = (const float*)d_in[2];
    const float*     bias  = (const float*)d_in[3];
    const float*     alpha = (const float*)d_in[4];
    float*           out   = (float*)d_out;

    cudaFuncSetAttribute(gemm_hmma, cudaFuncAttributeMaxDynamicSharedMemorySize,
                         GEMM_SMEM);

    cudaStream_t s2;
    cudaStreamCreateWithFlags(&s2, cudaStreamNonBlocking);
    cudaEvent_t e1, e2;
    cudaEventCreateWithFlags(&e1, cudaEventDisableTiming);
    cudaEventCreateWithFlags(&e2, cudaEventDisableTiming);

    setup_kernel<<<(N_NODES + 255) / 256, 256>>>(ei32, W);

    cudaEventRecord(e1, 0);
    cudaStreamWaitEvent(s2, e1, 0);
    gemm_hmma   <<<(N_NODES + 127) / 128, 256, GEMM_SMEM, s2>>>(x);

    fill_kernel <<<(N_EDGES + 255) / 256, 256>>>(ei32, ei64);
    dinv_kernel <<<(N_NODES + 255) / 256, 256>>>();
    scan_kernel <<<1, 128>>>();
    order_kernel<<<(N_NODES + 255) / 256, 256>>>();

    cudaEventRecord(e2, s2);
    cudaStreamWaitEvent(0, e2, 0);
    agg_kernel  <<<((size_t)N_NODES * 16 + 255) / 256, 256>>>(bias, alpha, out);
}

// round 14
// speedup vs baseline: 1.3543x; 1.3543x over previous
#include <cuda_runtime.h>
#include <cuda_fp16.h>
#include <cstdint>

#define N_NODES 100000
#define N_EDGES 1600000
#define IN_CH   256
#define HID     128
#define PAD     96          // max in-degree bucket (Poisson(16): P(>=96) ~ e^-92)

// ---------------- device scratch (no runtime allocation allowed) -------------
__device__ __half g_hh[(size_t)N_NODES * HID];  // x@W (unscaled), fp16
__device__ float  g_dinv[N_NODES];
__device__ int    g_cur[N_NODES];               // in-degree counters / cursors
__device__ int    g_psrc[(size_t)N_NODES * PAD];// padded neighbor lists
__device__ int    g_is64;
__device__ __half g_wt[HID * IN_CH];            // W^T fp16: [n][k]

// ---------------- 1. setup: zero counters + detect dtype + convert W ----------
__global__ void setup_kernel(const int* __restrict__ ei32,
                             const float* __restrict__ W) {
    int i = blockIdx.x * blockDim.x + threadIdx.x;
    if (i < N_NODES) g_cur[i] = 0;
    if (i < HID * IN_CH) {
        int n = i >> 8;           // 0..127
        int k = i & 255;          // 0..255
        g_wt[i] = __float2half_rn(W[k * HID + n]);
    }
    if (i == 0) {
        int all_zero = 1;
#pragma unroll
        for (int j = 0; j < 8; j++)
            if (ei32[2 * j + 1] != 0) all_zero = 0;
        g_is64 = all_zero;
    }
}

// ---------------- 2. bucket-fill padded neighbor lists -------------------------
__global__ void fill_kernel(const int* __restrict__ ei32,
                            const long long* __restrict__ ei64) {
    int e = blockIdx.x * blockDim.x + threadIdx.x;
    if (e < N_EDGES) {
        int r, c;
        if (g_is64) {
            r = (int)ei64[e];
            c = (int)ei64[N_EDGES + e];
        } else {
            r = ei32[e];
            c = ei32[N_EDGES + e];
        }
        int p = atomicAdd(&g_cur[c], 1);
        if (p < PAD) g_psrc[(size_t)c * PAD + p] = r;
    }
}

// ---------------- 3. counters -> dinv -----------------------------------------
__global__ void dinv_kernel() {
    int i = blockIdx.x * blockDim.x + threadIdx.x;
    if (i < N_NODES) g_dinv[i] = rsqrtf((float)(g_cur[i] + 1));  // +1 self loop
}

// ---------------- 4. HMMA GEMM: hh = x @ W (fp16 single-term) -----------------
#define KCH    32
#define NCHUNK (IN_CH / KCH)     // 8
#define LDA    40                // padded row: 80B (conflict-free for ldmatrix)
#define B_B    10240             // B tile byte offset within buffer
#define BUF_B  20480
#define GEMM_SMEM (2 * BUF_B)    // 40960 bytes

__device__ __forceinline__ uint32_t s2u(const void* p) {
    uint32_t a;
    asm("{ .reg .u64 t; cvta.to.shared.u64 t, %1; cvt.u32.u64 %0, t; }"
        : "=r"(a) : "l"(p));
    return a;
}
__device__ __forceinline__ void ldsm4(uint32_t& r0, uint32_t& r1,
                                      uint32_t& r2, uint32_t& r3, uint32_t a) {
    asm volatile("ldmatrix.sync.aligned.m8n8.x4.shared.b16 {%0,%1,%2,%3}, [%4];"
                 : "=r"(r0), "=r"(r1), "=r"(r2), "=r"(r3) : "r"(a));
}
__device__ __forceinline__ void mma_f16(float* c, const uint32_t* a,
                                        const uint32_t* b) {
    asm volatile(
        "mma.sync.aligned.m16n8k16.row.col.f32.f16.f16.f32 "
        "{%0,%1,%2,%3}, {%4,%5,%6,%7}, {%8,%9}, {%0,%1,%2,%3};"
        : "+f"(c[0]), "+f"(c[1]), "+f"(c[2]), "+f"(c[3])
        : "r"(a[0]), "r"(a[1]), "r"(a[2]), "r"(a[3]), "r"(b[0]), "r"(b[1]));
}
__device__ __forceinline__ void cpa16(uint32_t dst, const void* src) {
    asm volatile("cp.async.ca.shared.global [%0], [%1], 16;"
                 :: "r"(dst), "l"(src) : "memory");
}
__device__ __forceinline__ uint32_t pack_h(float x, float y) {
    __half2 h = __floats2half2_rn(x, y);
    return *(uint32_t*)&h;
}

__global__ __launch_bounds__(256, 2) void gemm_hmma(const float* __restrict__ x) {
    extern __shared__ char sm[];
    const uint32_t smb = s2u(sm);

    const int t    = threadIdx.x;
    const int w    = t >> 5;
    const int l    = t & 31;
    const int wm   = w >> 2;         // 0..1
    const int wn   = w & 3;          // 0..3
    const int row0 = blockIdx.x * 128;

    float acc[4][4][4];
#pragma unroll
    for (int i = 0; i < 4; i++)
#pragma unroll
        for (int j = 0; j < 4; j++)
#pragma unroll
            for (int r = 0; r < 4; r++) acc[i][j][r] = 0.f;

    // ---- x staging: warp-contiguous. thread -> (row base rb, quad q) ----
    const int q  = l & 7;                 // 0..7 : 16B quad within the 128B piece
    const int rb = w * 4 + (l >> 3);      // 0..31
    const float4* xsrc = (const float4*)(x + (size_t)(row0 + rb) * IN_CH) + q;
    bool av[4];
    uint32_t ast[4];
#pragma unroll
    for (int i = 0; i < 4; i++) {
        av[i]  = (row0 + rb + 32 * i) < N_NODES;
        ast[i] = (uint32_t)((rb + 32 * i) * 80 + q * 8);
    }

    // ---- W staging via cp.async ----
    const __half* w_src = g_wt + (t >> 1) * IN_CH + (t & 1) * 16;
    const uint32_t b_st = smb + B_B + (uint32_t)((t >> 1) * 80 + (t & 1) * 32);

    // ldmatrix per-lane base addresses (bytes within buffer 0)
    const int a_row = wm * 64 + (l & 15);
    const int a_k   = (l >> 4) * 8;
    const int b_row = wn * 32 + (l & 7) + ((l >> 4) << 3);
    const int b_k   = ((l >> 3) & 1) * 8;
    const uint32_t aH = smb + (a_row * LDA + a_k) * 2;
    const uint32_t bH = smb + B_B + (b_row * LDA + b_k) * 2;

    float4 xa[4];
#pragma unroll
    for (int i = 0; i < 4; i++) xa[i] = make_float4(0.f, 0.f, 0.f, 0.f);

    // ---- prologue: chunk 0 ----
    cpa16(b_st,      w_src);
    cpa16(b_st + 16, w_src + 8);
    asm volatile("cp.async.commit_group;" ::: "memory");
#pragma unroll
    for (int i = 0; i < 4; i++)
        if (av[i]) xa[i] = xsrc[i * 2048];
#pragma unroll
    for (int i = 0; i < 4; i++)
        *(uint2*)(sm + ast[i]) =
            make_uint2(pack_h(xa[i].x, xa[i].y), pack_h(xa[i].z, xa[i].w));
    asm volatile("cp.async.wait_group 0;" ::: "memory");
    __syncthreads();

    for (int c = 0; c < NCHUNK; c++) {
        const uint32_t cur = (uint32_t)(c & 1) * BUF_B;
        const uint32_t nxt = (uint32_t)((c + 1) & 1) * BUF_B;

        if (c < NCHUNK - 1) {
            const __half* wn_src = w_src + (c + 1) * KCH;
            cpa16(b_st + nxt,      wn_src);
            cpa16(b_st + nxt + 16, wn_src + 8);
            asm volatile("cp.async.commit_group;" ::: "memory");
#pragma unroll
            for (int i = 0; i < 4; i++)
                if (av[i]) xa[i] = xsrc[(c + 1) * 8 + i * 2048];
        }

        // ---- 2 k16 steps of MMAs on buffer `cur` ----
#pragma unroll
        for (int kk = 0; kk < 2; kk++) {
            const uint32_t kb = cur + kk * 32;
            uint32_t bh[4][2];
#pragma unroll
            for (int jp = 0; jp < 2; jp++) {
                const uint32_t off = kb + jp * 1280;   // 16 rows * 80B
                ldsm4(bh[2*jp][0], bh[2*jp][1], bh[2*jp+1][0], bh[2*jp+1][1],
                      bH + off);
            }
#pragma unroll
            for (int mi = 0; mi < 4; mi++) {
                const uint32_t off = kb + mi * 1280;
                uint32_t ah[4];
                ldsm4(ah[0], ah[1], ah[2], ah[3], aH + off);
#pragma unroll
                for (int nj = 0; nj < 4; nj++)
                    mma_f16(acc[mi][nj], ah, bh[nj]);
            }
        }

        if (c < NCHUNK - 1) {
#pragma unroll
            for (int i = 0; i < 4; i++)
                *(uint2*)(sm + nxt + ast[i]) =
                    make_uint2(pack_h(xa[i].x, xa[i].y), pack_h(xa[i].z, xa[i].w));
            asm volatile("cp.async.wait_group 0;" ::: "memory");
        }
        __syncthreads();
    }

    // ---- epilogue: fp16 store ----
    const int mrow = row0 + wm * 64 + (l >> 2);
    const int ncol = wn * 32 + (l & 3) * 2;
#pragma unroll
    for (int mi = 0; mi < 4; mi++) {
        const int r0 = mrow + mi * 16;
        const int r1 = r0 + 8;
#pragma unroll
        for (int nj = 0; nj < 4; nj++) {
            const int n0 = ncol + nj * 8;
            if (r0 < N_NODES)
                *(__half2*)(g_hh + (size_t)r0 * HID + n0) =
                    __floats2half2_rn(acc[mi][nj][0], acc[mi][nj][1]);
            if (r1 < N_NODES)
                *(__half2*)(g_hh + (size_t)r1 * HID + n0) =
                    __floats2half2_rn(acc[mi][nj][2], acc[mi][nj][3]);
        }
    }
}

// ---------------- 5. aggregate + bias + PReLU ----------------------------------
// Half-warp (16 lanes) per node; lane owns 8 channels (16B uint4 of fp16).
// unroll-8 -> up to 16 row-gathers in flight per warp.
__device__ __forceinline__ void h8(const uint4& u, float* f) {
    float2 p;
    p = __half22float2(*(const __half2*)&u.x); f[0] = p.x; f[1] = p.y;
    p = __half22float2(*(const __half2*)&u.y); f[2] = p.x; f[3] = p.y;
    p = __half22float2(*(const __half2*)&u.z); f[4] = p.x; f[5] = p.y;
    p = __half22float2(*(const __half2*)&u.w); f[6] = p.x; f[7] = p.y;
}

__global__ __launch_bounds__(256) void agg_kernel(const float* __restrict__ bias,
                                                  const float* __restrict__ alpha,
                                                  float* __restrict__ out) {
    int node = (blockIdx.x * blockDim.x + threadIdx.x) >> 4;
    int lane = threadIdx.x & 15;
    if (node >= N_NODES) return;

    const uint4* __restrict__ hhv = (const uint4*)g_hh;   // 16 uint4 per row
    int cnt = g_cur[node];
    if (cnt > PAD) cnt = PAD;
    const float di = g_dinv[node];
    const int*  nb = g_psrc + (size_t)node * PAD;

    // self-loop seed: h[i] * dinv[i]
    float acc[8], f[8];
    uint4 su = hhv[(size_t)node * 16 + lane];
    h8(su, acc);
#pragma unroll
    for (int i = 0; i < 8; i++) acc[i] *= di;

    int e = 0;
    for (; e + 8 <= cnt; e += 8) {
        int j[8]; uint4 u[8]; float dd[8];
#pragma unroll
        for (int i = 0; i < 8; i++) j[i] = nb[e + i];
#pragma unroll
        for (int i = 0; i < 8; i++) u[i] = hhv[(size_t)j[i] * 16 + lane];
#pragma unroll
        for (int i = 0; i < 8; i++) dd[i] = g_dinv[j[i]];
#pragma unroll
        for (int i = 0; i < 8; i++) {
            h8(u[i], f);
#pragma unroll
            for (int c = 0; c < 8; c++) acc[c] += f[c] * dd[i];
        }
    }
    for (; e + 2 <= cnt; e += 2) {
        int j0 = nb[e], j1 = nb[e + 1];
        uint4 u0 = hhv[(size_t)j0 * 16 + lane];
        uint4 u1 = hhv[(size_t)j1 * 16 + lane];
        float d0 = g_dinv[j0], d1 = g_dinv[j1];
        h8(u0, f);
#pragma unroll
        for (int c = 0; c < 8; c++) acc[c] += f[c] * d0;
        h8(u1, f);
#pragma unroll
        for (int c = 0; c < 8; c++) acc[c] += f[c] * d1;
    }
    if (e < cnt) {
        int j = nb[e];
        uint4 u = hhv[(size_t)j * 16 + lane];
        float dj = g_dinv[j];
        h8(u, f);
#pragma unroll
        for (int c = 0; c < 8; c++) acc[c] += f[c] * dj;
    }

    float4 b0 = ((const float4*)bias)[lane * 2];
    float4 b1 = ((const float4*)bias)[lane * 2 + 1];
    float4 a0 = ((const float4*)alpha)[lane * 2];
    float4 a1 = ((const float4*)alpha)[lane * 2 + 1];

    float4 r0, r1;
    r0.x = di * acc[0] + b0.x;  r0.x = (r0.x > 0.f) ? r0.x : a0.x * r0.x;
    r0.y = di * acc[1] + b0.y;  r0.y = (r0.y > 0.f) ? r0.y : a0.y * r0.y;
    r0.z = di * acc[2] + b0.z;  r0.z = (r0.z > 0.f) ? r0.z : a0.z * r0.z;
    r0.w = di * acc[3] + b0.w;  r0.w = (r0.w > 0.f) ? r0.w : a0.w * r0.w;
    r1.x = di * acc[4] + b1.x;  r1.x = (r1.x > 0.f) ? r1.x : a1.x * r1.x;
    r1.y = di * acc[5] + b1.y;  r1.y = (r1.y > 0.f) ? r1.y : a1.y * r1.y;
    r1.z = di * acc[6] + b1.z;  r1.z = (r1.z > 0.f) ? r1.z : a1.z * r1.z;
    r1.w = di * acc[7] + b1.w;  r1.w = (r1.w > 0.f) ? r1.w : a1.w * r1.w;

    ((float4*)out)[(size_t)node * 32 + lane * 2]     = r0;
    ((float4*)out)[(size_t)node * 32 + lane * 2 + 1] = r1;
}

// ---------------- launch --------------------------------------------------------
// Fork: gemm (tensor/L1-bound) runs concurrently with fill+dinv (L2-atomic-bound).
// Streams/events are created per call and NOT destroyed (destroying a capturing
// stream invalidates the capture; kernel_launch runs only ~twice, leak bounded).
extern "C" void kernel_launch(void* const* d_in, const int* in_sizes, int n_in,
                              void* d_out, int out_size) {
    const float*     x     = (const float*)d_in[0];
    const int*       ei32  = (const int*)d_in[1];
    const long long* ei64  = (const long long*)d_in[1];
    const float*     W     = (const float*)d_in[2];
    const float*     bias  = (const float*)d_in[3];
    const float*     alpha = (const float*)d_in[4];
    float*           out   = (float*)d_out;

    cudaFuncSetAttribute(gemm_hmma, cudaFuncAttributeMaxDynamicSharedMemorySize,
                         GEMM_SMEM);

    cudaStream_t s2;
    cudaStreamCreateWithFlags(&s2, cudaStreamNonBlocking);
    cudaEvent_t e1, e2;
    cudaEventCreateWithFlags(&e1, cudaEventDisableTiming);
    cudaEventCreateWithFlags(&e2, cudaEventDisableTiming);

    setup_kernel<<<(N_NODES + 255) / 256, 256>>>(ei32, W);

    cudaEventRecord(e1, 0);
    cudaStreamWaitEvent(s2, e1, 0);
    gemm_hmma   <<<(N_NODES + 127) / 128, 256, GEMM_SMEM, s2>>>(x);

    fill_kernel <<<(N_EDGES + 255) / 256, 256>>>(ei32, ei64);
    dinv_kernel <<<(N_NODES + 255) / 256, 256>>>();

    cudaEventRecord(e2, s2);
    cudaStreamWaitEvent(0, e2, 0);
    agg_kernel  <<<((size_t)N_NODES * 16 + 255) / 256, 256>>>(bias, alpha, out);
}